// round 12
// baseline (speedup 1.0000x reference)
#include <cuda_runtime.h>

#define BATCH 4
#define SEQ   2048
#define HID   1024
#define NHEAD 16
#define HDIM  64

// Scratch (static device globals — allowed; no runtime allocation)
__device__ float g_q[BATCH*NHEAD*SEQ*HDIM];
__device__ float g_k[BATCH*NHEAD*SEQ*HDIM];
__device__ float g_v[BATCH*NHEAD*SEQ*HDIM];
__device__ float g_attn[BATCH*SEQ*HID];

// ---------------------------------------------------------------------------
// Stage 1: QKV GEMM  (byte-identical to the R8/R10/R11 passing version)
// ---------------------------------------------------------------------------
__global__ __launch_bounds__(256) void qkv_gemm(const float* __restrict__ A,
                                                const float* __restrict__ W,
                                                const float* __restrict__ bias)
{
    const int K = HID;
    const int N = 3 * HID;
    __shared__ float As[8][128];
    __shared__ float Bs[8][128];

    const int tid = threadIdx.x;
    const int m0 = blockIdx.y * 128;
    const int n0 = blockIdx.x * 128;

    const int arow = tid >> 1;          // 0..127
    const int acol = (tid & 1) * 4;     // 0 or 4
    const int brow = tid >> 5;          // 0..7
    const int bcol = (tid & 31) * 4;    // 0..124

    const float* Ap = A + (m0 + arow) * K + acol;
    const float* Bp = W + brow * N + n0 + bcol;

    float acc[8][8] = {};
    const int ty = tid >> 4, tx = tid & 15;

    // stage tile 0
    float4 av = *(const float4*)(Ap);
    float4 bv = *(const float4*)(Bp);

    for (int k0 = 0; k0 < K; k0 += 8) {
        As[acol + 0][arow] = av.x;
        As[acol + 1][arow] = av.y;
        As[acol + 2][arow] = av.z;
        As[acol + 3][arow] = av.w;
        *(float4*)&Bs[brow][bcol] = bv;
        __syncthreads();

        if (k0 + 8 < K) {
            av = *(const float4*)(Ap + k0 + 8);
            bv = *(const float4*)(Bp + (long)(k0 + 8) * N);
        }

        #pragma unroll
        for (int kk = 0; kk < 8; kk++) {
            float4 a0 = *(const float4*)&As[kk][ty * 8];
            float4 a1 = *(const float4*)&As[kk][ty * 8 + 4];
            float4 b0 = *(const float4*)&Bs[kk][tx * 8];
            float4 b1 = *(const float4*)&Bs[kk][tx * 8 + 4];
            float a[8] = {a0.x,a0.y,a0.z,a0.w,a1.x,a1.y,a1.z,a1.w};
            float b[8] = {b0.x,b0.y,b0.z,b0.w,b1.x,b1.y,b1.z,b1.w};
            #pragma unroll
            for (int i = 0; i < 8; i++)
                #pragma unroll
                for (int j = 0; j < 8; j++)
                    acc[i][j] += a[i] * b[j];
        }
        __syncthreads();
    }

    #pragma unroll
    for (int i = 0; i < 8; i++) {
        const int m = m0 + ty * 8 + i;
        const int bb = m >> 11;          // / SEQ
        const int s  = m & 2047;
        #pragma unroll
        for (int j = 0; j < 8; j++) {
            const int n = n0 + tx * 8 + j;
            const float v = acc[i][j] + bias[n];
            const int which = n >> 10;
            const int rem = n & 1023;
            const int h = rem >> 6;
            const int d = rem & 63;
            const int idx = (((bb * NHEAD) + h) * SEQ + s) * HDIM + d;
            if (which == 0)      g_q[idx] = v;
            else if (which == 1) g_k[idx] = v;
            else                 g_v[idx] = v;
        }
    }
}

// ---------------------------------------------------------------------------
// Stage 2: causal flash attention, fp32, 128-query tiles, 8x4 per-thread,
// now with register-staged K/V prefetch (R8 GEMM pattern): STS staged ->
// sync -> LDG next tile -> compute -> sync. Identical arithmetic order to
// R11 (fingerprint must hold). V staged via STS.128; K scalar (transpose).
// smem: 64*132 + 2*64*68 + 128*68 floats = 103424 B.
// ---------------------------------------------------------------------------
__global__ __launch_bounds__(256, 2) void flash_attn()
{
    extern __shared__ float sm[];
    float (*QsT)[132] = (float(*)[132])sm;                          // [d][query]
    float (*KsT)[68]  = (float(*)[68])(sm + 64 * 132);              // [d][key]
    float (*Vs)[68]   = (float(*)[68])(sm + 64 * 132 + 64 * 68);    // [key][d]
    float (*Ps)[68]   = (float(*)[68])(sm + 64 * 132 + 2 * 64 * 68);// [query][key]

    const int b  = blockIdx.z;
    const int h  = blockIdx.y;
    const int qt = blockIdx.x;
    const int q0 = qt * 128;

    const float* Qg  = g_q + (((long)(b * NHEAD + h)) * SEQ + q0) * HDIM;
    const float* Kg0 = g_k + ((long)(b * NHEAD + h)) * SEQ * HDIM;
    const float* Vg0 = g_v + ((long)(b * NHEAD + h)) * SEQ * HDIM;

    const int tid = threadIdx.x;
    const int ty = tid >> 4, tx = tid & 15;
    const int rbase = 8 * ty;

    // load Q tile transposed: QsT[d][q] = Q[q][d]  (128 rows x 64 d)
    for (int i = tid; i < 128 * 64; i += 256) {
        const int r = i >> 6, c = i & 63;
        QsT[c][r] = Qg[i];
    }

    float m_i[8], l_i[8], acc[8][4];
    #pragma unroll
    for (int i = 0; i < 8; i++) {
        m_i[i] = -1e30f;
        l_i[i] = 0.0f;
        #pragma unroll
        for (int j = 0; j < 4; j++) acc[i][j] = 0.0f;
    }

    const float scale = 0.125f; // HD^-0.5
    const int ntiles = 2 * qt + 2;

    // stage tile 0 K/V into registers (float4 LDG)
    float4 kreg[4], vreg[4];
    #pragma unroll
    for (int p = 0; p < 4; p++) {
        const int idx = (p * 256 + tid) * 4;
        kreg[p] = *(const float4*)(Kg0 + idx);
        vreg[p] = *(const float4*)(Vg0 + idx);
    }

    for (int t = 0; t < ntiles; t++) {
        const int k0 = t * 64;

        // store staged registers to smem (K transposed, V row-major STS.128)
        #pragma unroll
        for (int p = 0; p < 4; p++) {
            const int idx = (p * 256 + tid) * 4;
            const int r = idx >> 6, c = idx & 63;
            KsT[c + 0][r] = kreg[p].x;
            KsT[c + 1][r] = kreg[p].y;
            KsT[c + 2][r] = kreg[p].z;
            KsT[c + 3][r] = kreg[p].w;
            *(float4*)&Vs[r][c] = vreg[p];
        }
        __syncthreads();   // staged tile visible (and Q load at t=0)

        // issue next tile's loads now; latency overlaps the compute below
        if (t + 1 < ntiles) {
            const long off = (long)(t + 1) * 64 * HDIM;
            #pragma unroll
            for (int p = 0; p < 4; p++) {
                const int idx = (p * 256 + tid) * 4;
                kreg[p] = *(const float4*)(Kg0 + off + idx);
                vreg[p] = *(const float4*)(Vg0 + off + idx);
            }
        }

        // S + softmax in two 4-row halves (limits live registers)
        #pragma unroll
        for (int hf = 0; hf < 2; hf++) {
            const int rb = rbase + 4 * hf;
            const bool active = (q0 + rb + 3 >= k0);
            if (active) {
                float s[4][4] = {};
                #pragma unroll 4
                for (int d = 0; d < 64; d++) {
                    const float4 q4 = *(const float4*)&QsT[d][rb];
                    const float4 k4 = *(const float4*)&KsT[d][4 * tx];
                    const float qv[4] = {q4.x, q4.y, q4.z, q4.w};
                    const float kv[4] = {k4.x, k4.y, k4.z, k4.w};
                    #pragma unroll
                    for (int i = 0; i < 4; i++)
                        #pragma unroll
                        for (int j = 0; j < 4; j++)
                            s[i][j] += qv[i] * kv[j];
                }
                #pragma unroll
                for (int i = 0; i < 4; i++) {
                    const int rg = q0 + rb + i;
                    #pragma unroll
                    for (int j = 0; j < 4; j++) {
                        const int cg = k0 + 4 * tx + j;
                        float val = s[i][j] * scale;
                        if (cg > rg) val = -1e30f;
                        s[i][j] = val;
                    }
                }
                #pragma unroll
                for (int i = 0; i < 4; i++) {
                    const int ii = 4 * hf + i;
                    float mx = fmaxf(fmaxf(s[i][0], s[i][1]), fmaxf(s[i][2], s[i][3]));
                    #pragma unroll
                    for (int off = 8; off >= 1; off >>= 1)
                        mx = fmaxf(mx, __shfl_xor_sync(0xffffffffu, mx, off));
                    const float mn = fmaxf(m_i[ii], mx);
                    const float corr = __expf(m_i[ii] - mn);
                    m_i[ii] = mn;
                    float rs = 0.0f;
                    #pragma unroll
                    for (int j = 0; j < 4; j++) {
                        s[i][j] = __expf(s[i][j] - mn);
                        rs += s[i][j];
                    }
                    #pragma unroll
                    for (int off = 8; off >= 1; off >>= 1)
                        rs += __shfl_xor_sync(0xffffffffu, rs, off);
                    l_i[ii] = l_i[ii] * corr + rs;
                    #pragma unroll
                    for (int j = 0; j < 4; j++) acc[ii][j] *= corr;
                }
                #pragma unroll
                for (int i = 0; i < 4; i++)
                    #pragma unroll
                    for (int j = 0; j < 4; j++)
                        Ps[rb + i][4 * tx + j] = s[i][j];
            } else {
                // fully masked half: P rows are exactly zero
                #pragma unroll
                for (int i = 0; i < 4; i++)
                    #pragma unroll
                    for (int j = 0; j < 4; j++)
                        Ps[rb + i][4 * tx + j] = 0.0f;
            }
        }
        __syncwarp();   // P rows exchanged only within the 16-lane tx group

        // O += P V : kk chunks of 4 (pv and vv both LDS.128)
        #pragma unroll 2
        for (int kk = 0; kk < 64; kk += 4) {
            float4 pv4[8];
            #pragma unroll
            for (int i = 0; i < 8; i++)
                pv4[i] = *(const float4*)&Ps[rbase + i][kk];
            float4 vv[4];
            #pragma unroll
            for (int c = 0; c < 4; c++)
                vv[c] = *(const float4*)&Vs[kk + c][4 * tx];
            #pragma unroll
            for (int i = 0; i < 8; i++) {
                const float pv[4] = {pv4[i].x, pv4[i].y, pv4[i].z, pv4[i].w};
                #pragma unroll
                for (int c = 0; c < 4; c++) {   // kk-sequential: same order as before
                    acc[i][0] += pv[c] * vv[c].x;
                    acc[i][1] += pv[c] * vv[c].y;
                    acc[i][2] += pv[c] * vv[c].z;
                    acc[i][3] += pv[c] * vv[c].w;
                }
            }
        }
        __syncthreads();   // all K/V reads done before next iteration's STS
    }

    // write out: g_attn[b][s][h*HD + d]
    #pragma unroll
    for (int i = 0; i < 8; i++) {
        const int rg = q0 + rbase + i;
        const float inv_l = 1.0f / l_i[i];
        #pragma unroll
        for (int j = 0; j < 4; j++) {
            g_attn[((long)(b * SEQ + rg)) * HID + h * HDIM + 4 * tx + j] =
                acc[i][j] * inv_l;
        }
    }
}

// ---------------------------------------------------------------------------
// Stage 3: output projection  (byte-identical to the R8/R10/R11 version)
// ---------------------------------------------------------------------------
__global__ __launch_bounds__(256) void out_gemm(const float* __restrict__ W,
                                                const float* __restrict__ bias,
                                                float* __restrict__ Out)
{
    const int K = HID;
    const int N = HID;
    __shared__ float As[8][128];
    __shared__ float Bs[8][128];

    const int tid = threadIdx.x;
    const int m0 = blockIdx.y * 128;
    const int n0 = blockIdx.x * 128;

    const int arow = tid >> 1;
    const int acol = (tid & 1) * 4;
    const int brow = tid >> 5;
    const int bcol = (tid & 31) * 4;

    const float* Ap = g_attn + (long)(m0 + arow) * K + acol;
    const float* Bp = W + brow * N + n0 + bcol;

    float acc[8][8] = {};
    const int ty = tid >> 4, tx = tid & 15;

    float4 av = *(const float4*)(Ap);
    float4 bv = *(const float4*)(Bp);

    for (int k0 = 0; k0 < K; k0 += 8) {
        As[acol + 0][arow] = av.x;
        As[acol + 1][arow] = av.y;
        As[acol + 2][arow] = av.z;
        As[acol + 3][arow] = av.w;
        *(float4*)&Bs[brow][bcol] = bv;
        __syncthreads();

        if (k0 + 8 < K) {
            av = *(const float4*)(Ap + k0 + 8);
            bv = *(const float4*)(Bp + (long)(k0 + 8) * N);
        }

        #pragma unroll
        for (int kk = 0; kk < 8; kk++) {
            float4 a0 = *(const float4*)&As[kk][ty * 8];
            float4 a1 = *(const float4*)&As[kk][ty * 8 + 4];
            float4 b0 = *(const float4*)&Bs[kk][tx * 8];
            float4 b1 = *(const float4*)&Bs[kk][tx * 8 + 4];
            float a[8] = {a0.x,a0.y,a0.z,a0.w,a1.x,a1.y,a1.z,a1.w};
            float b[8] = {b0.x,b0.y,b0.z,b0.w,b1.x,b1.y,b1.z,b1.w};
            #pragma unroll
            for (int i = 0; i < 8; i++)
                #pragma unroll
                for (int j = 0; j < 8; j++)
                    acc[i][j] += a[i] * b[j];
        }
        __syncthreads();
    }

    #pragma unroll
    for (int i = 0; i < 8; i++) {
        const int m = m0 + ty * 8 + i;
        #pragma unroll
        for (int j = 0; j < 8; j++) {
            const int n = n0 + tx * 8 + j;
            Out[(long)m * N + n] = acc[i][j] + bias[n];
        }
    }
}

// ---------------------------------------------------------------------------
extern "C" void kernel_launch(void* const* d_in, const int* in_sizes, int n_in,
                              void* d_out, int out_size)
{
    const float* x     = (const float*)d_in[0];
    const float* w_qkv = (const float*)d_in[1];
    const float* b_qkv = (const float*)d_in[2];
    const float* w_out = (const float*)d_in[3];
    const float* b_out = (const float*)d_in[4];
    float* out = (float*)d_out;

    // Stage 1: QKV projection + head scatter
    qkv_gemm<<<dim3(3 * HID / 128, (BATCH * SEQ) / 128), 256>>>(x, w_qkv, b_qkv);

    // Stage 2: causal flash attention (128-query tiles, K/V prefetch)
    const int shmem = (64 * 132 + 2 * 64 * 68 + 128 * 68) * (int)sizeof(float);
    cudaFuncSetAttribute(flash_attn,
                         cudaFuncAttributeMaxDynamicSharedMemorySize, shmem);
    flash_attn<<<dim3(SEQ / 128, NHEAD, BATCH), 256, shmem>>>();

    // Stage 3: output projection
    out_gemm<<<dim3(HID / 128, (BATCH * SEQ) / 128), 256>>>(w_out, b_out, out);
}

// round 13
// speedup vs baseline: 1.0308x; 1.0308x over previous
#include <cuda_runtime.h>

#define BATCH 4
#define SEQ   2048
#define HID   1024
#define NHEAD 16
#define HDIM  64

// Scratch (static device globals — allowed; no runtime allocation)
__device__ float g_q[BATCH*NHEAD*SEQ*HDIM];
__device__ float g_k[BATCH*NHEAD*SEQ*HDIM];
__device__ float g_v[BATCH*NHEAD*SEQ*HDIM];
__device__ float g_attn[BATCH*SEQ*HID];

// ---------------------------------------------------------------------------
// Stage 1: QKV GEMM, BK=16 (half the barriers of the BK=8 version), with
// register-staged prefetch. C[m][n] = x[m][:] . w_qkv[:][n] + b_qkv[n].
// 128x128 block tile, 256 threads, 8x8 per-thread tile. Epilogue scatters
// into head-major g_q/g_k/g_v (verified R1/R8 logic, unchanged).
// ---------------------------------------------------------------------------
__global__ __launch_bounds__(256) void qkv_gemm(const float* __restrict__ A,
                                                const float* __restrict__ W,
                                                const float* __restrict__ bias)
{
    const int K = HID;
    const int N = 3 * HID;
    __shared__ float As[16][128];
    __shared__ float Bs[16][128];

    const int tid = threadIdx.x;
    const int m0 = blockIdx.y * 128;
    const int n0 = blockIdx.x * 128;

    const int arow  = tid >> 1;          // 0..127
    const int acolb = (tid & 1) * 8;     // 0 or 8
    const int brow  = tid >> 5;          // 0..7 (also handles brow+8)
    const int bcol  = (tid & 31) * 4;    // 0..124

    const float* Ap = A + (m0 + arow) * K + acolb;
    const float* Bp = W + brow * N + n0 + bcol;

    float acc[8][8] = {};
    const int ty = tid >> 4, tx = tid & 15;

    // stage tile 0
    float4 av0 = *(const float4*)(Ap);
    float4 av1 = *(const float4*)(Ap + 4);
    float4 bv0 = *(const float4*)(Bp);
    float4 bv1 = *(const float4*)(Bp + (long)8 * N);

    for (int k0 = 0; k0 < K; k0 += 16) {
        // store staged registers to smem
        As[acolb + 0][arow] = av0.x;
        As[acolb + 1][arow] = av0.y;
        As[acolb + 2][arow] = av0.z;
        As[acolb + 3][arow] = av0.w;
        As[acolb + 4][arow] = av1.x;
        As[acolb + 5][arow] = av1.y;
        As[acolb + 6][arow] = av1.z;
        As[acolb + 7][arow] = av1.w;
        *(float4*)&Bs[brow    ][bcol] = bv0;
        *(float4*)&Bs[brow + 8][bcol] = bv1;
        __syncthreads();

        // issue next tile's loads now; latency overlaps the compute below
        if (k0 + 16 < K) {
            av0 = *(const float4*)(Ap + k0 + 16);
            av1 = *(const float4*)(Ap + k0 + 20);
            bv0 = *(const float4*)(Bp + (long)(k0 + 16) * N);
            bv1 = *(const float4*)(Bp + (long)(k0 + 24) * N);
        }

        #pragma unroll
        for (int kk = 0; kk < 16; kk++) {
            float4 a0 = *(const float4*)&As[kk][ty * 8];
            float4 a1 = *(const float4*)&As[kk][ty * 8 + 4];
            float4 b0 = *(const float4*)&Bs[kk][tx * 8];
            float4 b1 = *(const float4*)&Bs[kk][tx * 8 + 4];
            float a[8] = {a0.x,a0.y,a0.z,a0.w,a1.x,a1.y,a1.z,a1.w};
            float b[8] = {b0.x,b0.y,b0.z,b0.w,b1.x,b1.y,b1.z,b1.w};
            #pragma unroll
            for (int i = 0; i < 8; i++)
                #pragma unroll
                for (int j = 0; j < 8; j++)
                    acc[i][j] += a[i] * b[j];
        }
        __syncthreads();
    }

    #pragma unroll
    for (int i = 0; i < 8; i++) {
        const int m = m0 + ty * 8 + i;
        const int bb = m >> 11;          // / SEQ
        const int s  = m & 2047;
        #pragma unroll
        for (int j = 0; j < 8; j++) {
            const int n = n0 + tx * 8 + j;
            const float v = acc[i][j] + bias[n];
            const int which = n >> 10;
            const int rem = n & 1023;
            const int h = rem >> 6;
            const int d = rem & 63;
            const int idx = (((bb * NHEAD) + h) * SEQ + s) * HDIM + d;
            if (which == 0)      g_q[idx] = v;
            else if (which == 1) g_k[idx] = v;
            else                 g_v[idx] = v;
        }
    }
}

// ---------------------------------------------------------------------------
// Stage 2: causal flash attention — byte-identical to the R11 best version
// (128-query tiles, 8x4 per-thread, no K/V register prefetch).
// smem: 64*132 + 2*64*68 + 128*68 floats = 103424 B.
// ---------------------------------------------------------------------------
__global__ __launch_bounds__(256, 2) void flash_attn()
{
    extern __shared__ float sm[];
    float (*QsT)[132] = (float(*)[132])sm;                          // [d][query]
    float (*KsT)[68]  = (float(*)[68])(sm + 64 * 132);              // [d][key]
    float (*Vs)[68]   = (float(*)[68])(sm + 64 * 132 + 64 * 68);    // [key][d]
    float (*Ps)[68]   = (float(*)[68])(sm + 64 * 132 + 2 * 64 * 68);// [query][key]

    const int b  = blockIdx.z;
    const int h  = blockIdx.y;
    const int qt = blockIdx.x;
    const int q0 = qt * 128;

    const float* Qg  = g_q + (((long)(b * NHEAD + h)) * SEQ + q0) * HDIM;
    const float* Kg0 = g_k + ((long)(b * NHEAD + h)) * SEQ * HDIM;
    const float* Vg0 = g_v + ((long)(b * NHEAD + h)) * SEQ * HDIM;

    const int tid = threadIdx.x;
    const int ty = tid >> 4, tx = tid & 15;
    const int rbase = 8 * ty;

    // load Q tile transposed: QsT[d][q] = Q[q][d]  (128 rows x 64 d)
    for (int i = tid; i < 128 * 64; i += 256) {
        const int r = i >> 6, c = i & 63;
        QsT[c][r] = Qg[i];
    }

    float m_i[8], l_i[8], acc[8][4];
    #pragma unroll
    for (int i = 0; i < 8; i++) {
        m_i[i] = -1e30f;
        l_i[i] = 0.0f;
        #pragma unroll
        for (int j = 0; j < 4; j++) acc[i][j] = 0.0f;
    }

    const float scale = 0.125f; // HD^-0.5
    const int ntiles = 2 * qt + 2;

    for (int t = 0; t < ntiles; t++) {
        const int k0 = t * 64;
        __syncthreads();   // prior tile's K/V reads done (and Q load at t=0)
        for (int i = tid; i < 64 * 64; i += 256) {
            const int r = i >> 6, c = i & 63;
            KsT[c][r] = Kg0[k0 * HDIM + i];   // [d][key]
            Vs[r][c]  = Vg0[k0 * HDIM + i];   // [key][d]
        }
        __syncthreads();

        // S + softmax in two 4-row halves (limits live registers)
        #pragma unroll
        for (int hf = 0; hf < 2; hf++) {
            const int rb = rbase + 4 * hf;
            const bool active = (q0 + rb + 3 >= k0);
            if (active) {
                float s[4][4] = {};
                #pragma unroll 4
                for (int d = 0; d < 64; d++) {
                    const float4 q4 = *(const float4*)&QsT[d][rb];
                    const float4 k4 = *(const float4*)&KsT[d][4 * tx];
                    const float qv[4] = {q4.x, q4.y, q4.z, q4.w};
                    const float kv[4] = {k4.x, k4.y, k4.z, k4.w};
                    #pragma unroll
                    for (int i = 0; i < 4; i++)
                        #pragma unroll
                        for (int j = 0; j < 4; j++)
                            s[i][j] += qv[i] * kv[j];
                }
                #pragma unroll
                for (int i = 0; i < 4; i++) {
                    const int rg = q0 + rb + i;
                    #pragma unroll
                    for (int j = 0; j < 4; j++) {
                        const int cg = k0 + 4 * tx + j;
                        float val = s[i][j] * scale;
                        if (cg > rg) val = -1e30f;
                        s[i][j] = val;
                    }
                }
                #pragma unroll
                for (int i = 0; i < 4; i++) {
                    const int ii = 4 * hf + i;
                    float mx = fmaxf(fmaxf(s[i][0], s[i][1]), fmaxf(s[i][2], s[i][3]));
                    #pragma unroll
                    for (int off = 8; off >= 1; off >>= 1)
                        mx = fmaxf(mx, __shfl_xor_sync(0xffffffffu, mx, off));
                    const float mn = fmaxf(m_i[ii], mx);
                    const float corr = __expf(m_i[ii] - mn);
                    m_i[ii] = mn;
                    float rs = 0.0f;
                    #pragma unroll
                    for (int j = 0; j < 4; j++) {
                        s[i][j] = __expf(s[i][j] - mn);
                        rs += s[i][j];
                    }
                    #pragma unroll
                    for (int off = 8; off >= 1; off >>= 1)
                        rs += __shfl_xor_sync(0xffffffffu, rs, off);
                    l_i[ii] = l_i[ii] * corr + rs;
                    #pragma unroll
                    for (int j = 0; j < 4; j++) acc[ii][j] *= corr;
                }
                #pragma unroll
                for (int i = 0; i < 4; i++)
                    #pragma unroll
                    for (int j = 0; j < 4; j++)
                        Ps[rb + i][4 * tx + j] = s[i][j];
            } else {
                // fully masked half: P rows are exactly zero
                #pragma unroll
                for (int i = 0; i < 4; i++)
                    #pragma unroll
                    for (int j = 0; j < 4; j++)
                        Ps[rb + i][4 * tx + j] = 0.0f;
            }
        }
        __syncwarp();   // P rows exchanged only within the 16-lane tx group

        // O += P V : kk chunks of 4 (pv and vv both LDS.128)
        #pragma unroll 2
        for (int kk = 0; kk < 64; kk += 4) {
            float4 pv4[8];
            #pragma unroll
            for (int i = 0; i < 8; i++)
                pv4[i] = *(const float4*)&Ps[rbase + i][kk];
            float4 vv[4];
            #pragma unroll
            for (int c = 0; c < 4; c++)
                vv[c] = *(const float4*)&Vs[kk + c][4 * tx];
            #pragma unroll
            for (int i = 0; i < 8; i++) {
                const float pv[4] = {pv4[i].x, pv4[i].y, pv4[i].z, pv4[i].w};
                #pragma unroll
                for (int c = 0; c < 4; c++) {   // kk-sequential: same order as before
                    acc[i][0] += pv[c] * vv[c].x;
                    acc[i][1] += pv[c] * vv[c].y;
                    acc[i][2] += pv[c] * vv[c].z;
                    acc[i][3] += pv[c] * vv[c].w;
                }
            }
        }
        __syncwarp();   // own P rows fully consumed before next overwrite
    }

    // write out: g_attn[b][s][h*HD + d]
    #pragma unroll
    for (int i = 0; i < 8; i++) {
        const int rg = q0 + rbase + i;
        const float inv_l = 1.0f / l_i[i];
        #pragma unroll
        for (int j = 0; j < 4; j++) {
            g_attn[((long)(b * SEQ + rg)) * HID + h * HDIM + 4 * tx + j] =
                acc[i][j] * inv_l;
        }
    }
}

// ---------------------------------------------------------------------------
// Stage 3: output projection, BK=16 (same treatment as qkv_gemm).
// ---------------------------------------------------------------------------
__global__ __launch_bounds__(256) void out_gemm(const float* __restrict__ W,
                                                const float* __restrict__ bias,
                                                float* __restrict__ Out)
{
    const int K = HID;
    const int N = HID;
    __shared__ float As[16][128];
    __shared__ float Bs[16][128];

    const int tid = threadIdx.x;
    const int m0 = blockIdx.y * 128;
    const int n0 = blockIdx.x * 128;

    const int arow  = tid >> 1;
    const int acolb = (tid & 1) * 8;
    const int brow  = tid >> 5;
    const int bcol  = (tid & 31) * 4;

    const float* Ap = g_attn + (long)(m0 + arow) * K + acolb;
    const float* Bp = W + brow * N + n0 + bcol;

    float acc[8][8] = {};
    const int ty = tid >> 4, tx = tid & 15;

    float4 av0 = *(const float4*)(Ap);
    float4 av1 = *(const float4*)(Ap + 4);
    float4 bv0 = *(const float4*)(Bp);
    float4 bv1 = *(const float4*)(Bp + (long)8 * N);

    for (int k0 = 0; k0 < K; k0 += 16) {
        As[acolb + 0][arow] = av0.x;
        As[acolb + 1][arow] = av0.y;
        As[acolb + 2][arow] = av0.z;
        As[acolb + 3][arow] = av0.w;
        As[acolb + 4][arow] = av1.x;
        As[acolb + 5][arow] = av1.y;
        As[acolb + 6][arow] = av1.z;
        As[acolb + 7][arow] = av1.w;
        *(float4*)&Bs[brow    ][bcol] = bv0;
        *(float4*)&Bs[brow + 8][bcol] = bv1;
        __syncthreads();

        if (k0 + 16 < K) {
            av0 = *(const float4*)(Ap + k0 + 16);
            av1 = *(const float4*)(Ap + k0 + 20);
            bv0 = *(const float4*)(Bp + (long)(k0 + 16) * N);
            bv1 = *(const float4*)(Bp + (long)(k0 + 24) * N);
        }

        #pragma unroll
        for (int kk = 0; kk < 16; kk++) {
            float4 a0 = *(const float4*)&As[kk][ty * 8];
            float4 a1 = *(const float4*)&As[kk][ty * 8 + 4];
            float4 b0 = *(const float4*)&Bs[kk][tx * 8];
            float4 b1 = *(const float4*)&Bs[kk][tx * 8 + 4];
            float a[8] = {a0.x,a0.y,a0.z,a0.w,a1.x,a1.y,a1.z,a1.w};
            float b[8] = {b0.x,b0.y,b0.z,b0.w,b1.x,b1.y,b1.z,b1.w};
            #pragma unroll
            for (int i = 0; i < 8; i++)
                #pragma unroll
                for (int j = 0; j < 8; j++)
                    acc[i][j] += a[i] * b[j];
        }
        __syncthreads();
    }

    #pragma unroll
    for (int i = 0; i < 8; i++) {
        const int m = m0 + ty * 8 + i;
        #pragma unroll
        for (int j = 0; j < 8; j++) {
            const int n = n0 + tx * 8 + j;
            Out[(long)m * N + n] = acc[i][j] + bias[n];
        }
    }
}

// ---------------------------------------------------------------------------
extern "C" void kernel_launch(void* const* d_in, const int* in_sizes, int n_in,
                              void* d_out, int out_size)
{
    const float* x     = (const float*)d_in[0];
    const float* w_qkv = (const float*)d_in[1];
    const float* b_qkv = (const float*)d_in[2];
    const float* w_out = (const float*)d_in[3];
    const float* b_out = (const float*)d_in[4];
    float* out = (float*)d_out;

    // Stage 1: QKV projection + head scatter (BK=16)
    qkv_gemm<<<dim3(3 * HID / 128, (BATCH * SEQ) / 128), 256>>>(x, w_qkv, b_qkv);

    // Stage 2: causal flash attention (R11-exact)
    const int shmem = (64 * 132 + 2 * 64 * 68 + 128 * 68) * (int)sizeof(float);
    cudaFuncSetAttribute(flash_attn,
                         cudaFuncAttributeMaxDynamicSharedMemorySize, shmem);
    flash_attn<<<dim3(SEQ / 128, NHEAD, BATCH), 256, shmem>>>();

    // Stage 3: output projection (BK=16)
    out_gemm<<<dim3(HID / 128, (BATCH * SEQ) / 128), 256>>>(w_out, b_out, out);
}

// round 14
// speedup vs baseline: 1.0693x; 1.0374x over previous
#include <cuda_runtime.h>

#define BATCH 4
#define SEQ   2048
#define HID   1024
#define NHEAD 16
#define HDIM  64

// Scratch (static device globals — allowed; no runtime allocation)
__device__ float g_q[BATCH*NHEAD*SEQ*HDIM];
__device__ float g_k[BATCH*NHEAD*SEQ*HDIM];
__device__ float g_v[BATCH*NHEAD*SEQ*HDIM];
__device__ float g_attn[BATCH*SEQ*HID];

// ---------------------------------------------------------------------------
// Stage 1: QKV GEMM, BK=16 (byte-identical to the R13 passing version)
// ---------------------------------------------------------------------------
__global__ __launch_bounds__(256) void qkv_gemm(const float* __restrict__ A,
                                                const float* __restrict__ W,
                                                const float* __restrict__ bias)
{
    const int K = HID;
    const int N = 3 * HID;
    __shared__ float As[16][128];
    __shared__ float Bs[16][128];

    const int tid = threadIdx.x;
    const int m0 = blockIdx.y * 128;
    const int n0 = blockIdx.x * 128;

    const int arow  = tid >> 1;          // 0..127
    const int acolb = (tid & 1) * 8;     // 0 or 8
    const int brow  = tid >> 5;          // 0..7 (also handles brow+8)
    const int bcol  = (tid & 31) * 4;    // 0..124

    const float* Ap = A + (m0 + arow) * K + acolb;
    const float* Bp = W + brow * N + n0 + bcol;

    float acc[8][8] = {};
    const int ty = tid >> 4, tx = tid & 15;

    // stage tile 0
    float4 av0 = *(const float4*)(Ap);
    float4 av1 = *(const float4*)(Ap + 4);
    float4 bv0 = *(const float4*)(Bp);
    float4 bv1 = *(const float4*)(Bp + (long)8 * N);

    for (int k0 = 0; k0 < K; k0 += 16) {
        As[acolb + 0][arow] = av0.x;
        As[acolb + 1][arow] = av0.y;
        As[acolb + 2][arow] = av0.z;
        As[acolb + 3][arow] = av0.w;
        As[acolb + 4][arow] = av1.x;
        As[acolb + 5][arow] = av1.y;
        As[acolb + 6][arow] = av1.z;
        As[acolb + 7][arow] = av1.w;
        *(float4*)&Bs[brow    ][bcol] = bv0;
        *(float4*)&Bs[brow + 8][bcol] = bv1;
        __syncthreads();

        if (k0 + 16 < K) {
            av0 = *(const float4*)(Ap + k0 + 16);
            av1 = *(const float4*)(Ap + k0 + 20);
            bv0 = *(const float4*)(Bp + (long)(k0 + 16) * N);
            bv1 = *(const float4*)(Bp + (long)(k0 + 24) * N);
        }

        #pragma unroll
        for (int kk = 0; kk < 16; kk++) {
            float4 a0 = *(const float4*)&As[kk][ty * 8];
            float4 a1 = *(const float4*)&As[kk][ty * 8 + 4];
            float4 b0 = *(const float4*)&Bs[kk][tx * 8];
            float4 b1 = *(const float4*)&Bs[kk][tx * 8 + 4];
            float a[8] = {a0.x,a0.y,a0.z,a0.w,a1.x,a1.y,a1.z,a1.w};
            float b[8] = {b0.x,b0.y,b0.z,b0.w,b1.x,b1.y,b1.z,b1.w};
            #pragma unroll
            for (int i = 0; i < 8; i++)
                #pragma unroll
                for (int j = 0; j < 8; j++)
                    acc[i][j] += a[i] * b[j];
        }
        __syncthreads();
    }

    #pragma unroll
    for (int i = 0; i < 8; i++) {
        const int m = m0 + ty * 8 + i;
        const int bb = m >> 11;          // / SEQ
        const int s  = m & 2047;
        #pragma unroll
        for (int j = 0; j < 8; j++) {
            const int n = n0 + tx * 8 + j;
            const float v = acc[i][j] + bias[n];
            const int which = n >> 10;
            const int rem = n & 1023;
            const int h = rem >> 6;
            const int d = rem & 63;
            const int idx = (((bb * NHEAD) + h) * SEQ + s) * HDIM + d;
            if (which == 0)      g_q[idx] = v;
            else if (which == 1) g_k[idx] = v;
            else                 g_v[idx] = v;
        }
    }
}

// ---------------------------------------------------------------------------
// Stage 2: causal flash attention, fp32, 128-query tiles, 8x4 per-thread.
// CHANGE vs R11/R13: the S=QK^T loop is FUSED across all 8 rows (one d-loop,
// K fragment loaded once instead of twice). Softmax / mask / P-write keep
// the exact per-half structure and active-guards. Arithmetic order per row
// unchanged.
// smem: 64*132 + 2*64*68 + 128*68 floats = 103424 B.
// ---------------------------------------------------------------------------
__global__ __launch_bounds__(256, 2) void flash_attn()
{
    extern __shared__ float sm[];
    float (*QsT)[132] = (float(*)[132])sm;                          // [d][query]
    float (*KsT)[68]  = (float(*)[68])(sm + 64 * 132);              // [d][key]
    float (*Vs)[68]   = (float(*)[68])(sm + 64 * 132 + 64 * 68);    // [key][d]
    float (*Ps)[68]   = (float(*)[68])(sm + 64 * 132 + 2 * 64 * 68);// [query][key]

    const int b  = blockIdx.z;
    const int h  = blockIdx.y;
    const int qt = blockIdx.x;
    const int q0 = qt * 128;

    const float* Qg  = g_q + (((long)(b * NHEAD + h)) * SEQ + q0) * HDIM;
    const float* Kg0 = g_k + ((long)(b * NHEAD + h)) * SEQ * HDIM;
    const float* Vg0 = g_v + ((long)(b * NHEAD + h)) * SEQ * HDIM;

    const int tid = threadIdx.x;
    const int ty = tid >> 4, tx = tid & 15;
    const int rbase = 8 * ty;

    // load Q tile transposed: QsT[d][q] = Q[q][d]  (128 rows x 64 d)
    for (int i = tid; i < 128 * 64; i += 256) {
        const int r = i >> 6, c = i & 63;
        QsT[c][r] = Qg[i];
    }

    float m_i[8], l_i[8], acc[8][4];
    #pragma unroll
    for (int i = 0; i < 8; i++) {
        m_i[i] = -1e30f;
        l_i[i] = 0.0f;
        #pragma unroll
        for (int j = 0; j < 4; j++) acc[i][j] = 0.0f;
    }

    const float scale = 0.125f; // HD^-0.5
    const int ntiles = 2 * qt + 2;

    for (int t = 0; t < ntiles; t++) {
        const int k0 = t * 64;
        __syncthreads();   // prior tile's K/V reads done (and Q load at t=0)
        for (int i = tid; i < 64 * 64; i += 256) {
            const int r = i >> 6, c = i & 63;
            KsT[c][r] = Kg0[k0 * HDIM + i];   // [d][key]
            Vs[r][c]  = Vg0[k0 * HDIM + i];   // [key][d]
        }
        __syncthreads();

        // S = Q K^T fused over all 8 rows: per d, 2 q-float4 + 1 k-float4
        float s[8][4];
        #pragma unroll
        for (int i = 0; i < 8; i++)
            #pragma unroll
            for (int j = 0; j < 4; j++) s[i][j] = 0.0f;

        #pragma unroll 4
        for (int d = 0; d < 64; d++) {
            const float4 qa = *(const float4*)&QsT[d][rbase];
            const float4 qb = *(const float4*)&QsT[d][rbase + 4];
            const float4 k4 = *(const float4*)&KsT[d][4 * tx];
            const float qv[8] = {qa.x, qa.y, qa.z, qa.w, qb.x, qb.y, qb.z, qb.w};
            const float kv[4] = {k4.x, k4.y, k4.z, k4.w};
            #pragma unroll
            for (int i = 0; i < 8; i++)
                #pragma unroll
                for (int j = 0; j < 4; j++)
                    s[i][j] += qv[i] * kv[j];
        }

        // mask + softmax + P write, per 4-row half (guards preserved)
        #pragma unroll
        for (int hf = 0; hf < 2; hf++) {
            const int rb = rbase + 4 * hf;
            const bool active = (q0 + rb + 3 >= k0);
            if (active) {
                #pragma unroll
                for (int i = 0; i < 4; i++) {
                    const int ii = 4 * hf + i;
                    const int rg = q0 + rb + i;
                    #pragma unroll
                    for (int j = 0; j < 4; j++) {
                        const int cg = k0 + 4 * tx + j;
                        float val = s[ii][j] * scale;
                        if (cg > rg) val = -1e30f;
                        s[ii][j] = val;
                    }
                }
                #pragma unroll
                for (int i = 0; i < 4; i++) {
                    const int ii = 4 * hf + i;
                    float mx = fmaxf(fmaxf(s[ii][0], s[ii][1]),
                                     fmaxf(s[ii][2], s[ii][3]));
                    #pragma unroll
                    for (int off = 8; off >= 1; off >>= 1)
                        mx = fmaxf(mx, __shfl_xor_sync(0xffffffffu, mx, off));
                    const float mn = fmaxf(m_i[ii], mx);
                    const float corr = __expf(m_i[ii] - mn);
                    m_i[ii] = mn;
                    float rs = 0.0f;
                    #pragma unroll
                    for (int j = 0; j < 4; j++) {
                        s[ii][j] = __expf(s[ii][j] - mn);
                        rs += s[ii][j];
                    }
                    #pragma unroll
                    for (int off = 8; off >= 1; off >>= 1)
                        rs += __shfl_xor_sync(0xffffffffu, rs, off);
                    l_i[ii] = l_i[ii] * corr + rs;
                    #pragma unroll
                    for (int j = 0; j < 4; j++) acc[ii][j] *= corr;
                }
                #pragma unroll
                for (int i = 0; i < 4; i++)
                    #pragma unroll
                    for (int j = 0; j < 4; j++)
                        Ps[rb + i][4 * tx + j] = s[4 * hf + i][j];
            } else {
                // fully masked half: P rows are exactly zero
                #pragma unroll
                for (int i = 0; i < 4; i++)
                    #pragma unroll
                    for (int j = 0; j < 4; j++)
                        Ps[rb + i][4 * tx + j] = 0.0f;
            }
        }
        __syncwarp();   // P rows exchanged only within the 16-lane tx group

        // O += P V : kk chunks of 4 (pv and vv both LDS.128)
        #pragma unroll 2
        for (int kk = 0; kk < 64; kk += 4) {
            float4 pv4[8];
            #pragma unroll
            for (int i = 0; i < 8; i++)
                pv4[i] = *(const float4*)&Ps[rbase + i][kk];
            float4 vv[4];
            #pragma unroll
            for (int c = 0; c < 4; c++)
                vv[c] = *(const float4*)&Vs[kk + c][4 * tx];
            #pragma unroll
            for (int i = 0; i < 8; i++) {
                const float pv[4] = {pv4[i].x, pv4[i].y, pv4[i].z, pv4[i].w};
                #pragma unroll
                for (int c = 0; c < 4; c++) {   // kk-sequential: same order as before
                    acc[i][0] += pv[c] * vv[c].x;
                    acc[i][1] += pv[c] * vv[c].y;
                    acc[i][2] += pv[c] * vv[c].z;
                    acc[i][3] += pv[c] * vv[c].w;
                }
            }
        }
        __syncwarp();   // own P rows fully consumed before next overwrite
    }

    // write out: g_attn[b][s][h*HD + d]
    #pragma unroll
    for (int i = 0; i < 8; i++) {
        const int rg = q0 + rbase + i;
        const float inv_l = 1.0f / l_i[i];
        #pragma unroll
        for (int j = 0; j < 4; j++) {
            g_attn[((long)(b * SEQ + rg)) * HID + h * HDIM + 4 * tx + j] =
                acc[i][j] * inv_l;
        }
    }
}

// ---------------------------------------------------------------------------
// Stage 3: output projection, BK=16 (byte-identical to the R13 version)
// ---------------------------------------------------------------------------
__global__ __launch_bounds__(256) void out_gemm(const float* __restrict__ W,
                                                const float* __restrict__ bias,
                                                float* __restrict__ Out)
{
    const int K = HID;
    const int N = HID;
    __shared__ float As[16][128];
    __shared__ float Bs[16][128];

    const int tid = threadIdx.x;
    const int m0 = blockIdx.y * 128;
    const int n0 = blockIdx.x * 128;

    const int arow  = tid >> 1;
    const int acolb = (tid & 1) * 8;
    const int brow  = tid >> 5;
    const int bcol  = (tid & 31) * 4;

    const float* Ap = g_attn + (long)(m0 + arow) * K + acolb;
    const float* Bp = W + brow * N + n0 + bcol;

    float acc[8][8] = {};
    const int ty = tid >> 4, tx = tid & 15;

    float4 av0 = *(const float4*)(Ap);
    float4 av1 = *(const float4*)(Ap + 4);
    float4 bv0 = *(const float4*)(Bp);
    float4 bv1 = *(const float4*)(Bp + (long)8 * N);

    for (int k0 = 0; k0 < K; k0 += 16) {
        As[acolb + 0][arow] = av0.x;
        As[acolb + 1][arow] = av0.y;
        As[acolb + 2][arow] = av0.z;
        As[acolb + 3][arow] = av0.w;
        As[acolb + 4][arow] = av1.x;
        As[acolb + 5][arow] = av1.y;
        As[acolb + 6][arow] = av1.z;
        As[acolb + 7][arow] = av1.w;
        *(float4*)&Bs[brow    ][bcol] = bv0;
        *(float4*)&Bs[brow + 8][bcol] = bv1;
        __syncthreads();

        if (k0 + 16 < K) {
            av0 = *(const float4*)(Ap + k0 + 16);
            av1 = *(const float4*)(Ap + k0 + 20);
            bv0 = *(const float4*)(Bp + (long)(k0 + 16) * N);
            bv1 = *(const float4*)(Bp + (long)(k0 + 24) * N);
        }

        #pragma unroll
        for (int kk = 0; kk < 16; kk++) {
            float4 a0 = *(const float4*)&As[kk][ty * 8];
            float4 a1 = *(const float4*)&As[kk][ty * 8 + 4];
            float4 b0 = *(const float4*)&Bs[kk][tx * 8];
            float4 b1 = *(const float4*)&Bs[kk][tx * 8 + 4];
            float a[8] = {a0.x,a0.y,a0.z,a0.w,a1.x,a1.y,a1.z,a1.w};
            float b[8] = {b0.x,b0.y,b0.z,b0.w,b1.x,b1.y,b1.z,b1.w};
            #pragma unroll
            for (int i = 0; i < 8; i++)
                #pragma unroll
                for (int j = 0; j < 8; j++)
                    acc[i][j] += a[i] * b[j];
        }
        __syncthreads();
    }

    #pragma unroll
    for (int i = 0; i < 8; i++) {
        const int m = m0 + ty * 8 + i;
        #pragma unroll
        for (int j = 0; j < 8; j++) {
            const int n = n0 + tx * 8 + j;
            Out[(long)m * N + n] = acc[i][j] + bias[n];
        }
    }
}

// ---------------------------------------------------------------------------
extern "C" void kernel_launch(void* const* d_in, const int* in_sizes, int n_in,
                              void* d_out, int out_size)
{
    const float* x     = (const float*)d_in[0];
    const float* w_qkv = (const float*)d_in[1];
    const float* b_qkv = (const float*)d_in[2];
    const float* w_out = (const float*)d_in[3];
    const float* b_out = (const float*)d_in[4];
    float* out = (float*)d_out;

    // Stage 1: QKV projection + head scatter (BK=16)
    qkv_gemm<<<dim3(3 * HID / 128, (BATCH * SEQ) / 128), 256>>>(x, w_qkv, b_qkv);

    // Stage 2: causal flash attention (fused S-phase)
    const int shmem = (64 * 132 + 2 * 64 * 68 + 128 * 68) * (int)sizeof(float);
    cudaFuncSetAttribute(flash_attn,
                         cudaFuncAttributeMaxDynamicSharedMemorySize, shmem);
    flash_attn<<<dim3(SEQ / 128, NHEAD, BATCH), 256, shmem>>>();

    // Stage 3: output projection (BK=16)
    out_gemm<<<dim3(HID / 128, (BATCH * SEQ) / 128), 256>>>(w_out, b_out, out);
}